// round 5
// baseline (speedup 1.0000x reference)
#include <cuda_runtime.h>
#include <cuda_fp16.h>
#include <cstdint>

// ---------------- problem constants ----------------
#define NV 32768
#define NC 8192
#define DIM 64
#define Q_ELEMS (NV * DIM)
#define OFF_VQ Q_ELEMS
#define OFF_COMMIT (Q_ELEMS + 1)
#define OFF_IDX (Q_ELEMS + 2)

#define KP_BYTES 144    // padded smem row stride: 128B data + 16B pad (conflict-free ldsm)
#define TILE_M 128
#define TILE_N 64
#define NT (NC / TILE_N)        // 128 tiles
#define M_BLOCKS (NV / TILE_M)  // 256 CTAs
#define TAU 0.3f

// dynamic smem: A 128*144=18432 | B stage0 64*144=9216 | B stage1 | esq 2*256
#define SM_A 0
#define SM_B 18432
#define SM_BSTRIDE 9216
#define SM_ESQ 36864
#define DYN_SMEM 37632

// ---------------- device scratch ----------------
__device__ __align__(16) __half g_zh[NV * DIM];   // 4 MB
__device__ __align__(16) __half g_eh[NC * DIM];   // 1 MB
__device__ __align__(16) float g_esq[NC];
__device__ int g_bidx[NV];
__device__ int g_list[NV];
__device__ int g_count;
__device__ float g_partial[M_BLOCKS];

// ---------------- PTX helpers (baseline sm_80+ features only) ----------------
__device__ __forceinline__ uint32_t smem_u32(const void* p) {
    uint32_t a;
    asm("{ .reg .u64 t; cvta.to.shared.u64 t, %1; cvt.u32.u64 %0, t; }" : "=r"(a) : "l"(p));
    return a;
}
__device__ __forceinline__ void cpa16(uint32_t dst, const void* src) {
    asm volatile("cp.async.cg.shared.global [%0], [%1], 16;" :: "r"(dst), "l"(src));
}
#define CP_COMMIT() asm volatile("cp.async.commit_group;" ::: "memory")
#define CP_WAIT(n) asm volatile("cp.async.wait_group %0;" :: "n"(n) : "memory")

__device__ __forceinline__ void ldsm4(uint32_t& r0, uint32_t& r1, uint32_t& r2,
                                      uint32_t& r3, uint32_t addr) {
    asm volatile("ldmatrix.sync.aligned.m8n8.x4.shared.b16 {%0,%1,%2,%3}, [%4];"
                 : "=r"(r0), "=r"(r1), "=r"(r2), "=r"(r3) : "r"(addr));
}
__device__ __forceinline__ void mma16816(float* c, const uint32_t* a, uint32_t b0,
                                         uint32_t b1) {
    asm volatile(
        "mma.sync.aligned.m16n8k16.row.col.f32.f16.f16.f32 "
        "{%0,%1,%2,%3}, {%4,%5,%6,%7}, {%8,%9}, {%0,%1,%2,%3};"
        : "+f"(c[0]), "+f"(c[1]), "+f"(c[2]), "+f"(c[3])
        : "r"(a[0]), "r"(a[1]), "r"(a[2]), "r"(a[3]), "r"(b0), "r"(b1));
}

// ---------------- prep: codebook -> fp16 + exact esq ----------------
__global__ void prep_emb_kernel(const float* __restrict__ emb) {
    int c = blockIdx.x * blockDim.x + threadIdx.x;
    if (c == 0) g_count = 0;
    if (c >= NC) return;
    const float4* row = reinterpret_cast<const float4*>(emb + (size_t)c * DIM);
    __half2* dst = reinterpret_cast<__half2*>(g_eh + (size_t)c * DIM);
    float s = 0.f;
#pragma unroll
    for (int i = 0; i < 16; i++) {
        float4 v = row[i];
        s += v.x * v.x + v.y * v.y + v.z * v.z + v.w * v.w;
        dst[2 * i] = __halves2half2(__float2half_rn(v.x), __float2half_rn(v.y));
        dst[2 * i + 1] = __halves2half2(__float2half_rn(v.z), __float2half_rn(v.w));
    }
    g_esq[c] = s;
}

// ---------------- prep: z -> fp16 ----------------
__global__ void prep_z_kernel(const float* __restrict__ z) {
    int v = blockIdx.x * blockDim.x + threadIdx.x;
    if (v >= NV) return;
    const float4* row = reinterpret_cast<const float4*>(z + (size_t)v * DIM);
    __half2* dst = reinterpret_cast<__half2*>(g_zh + (size_t)v * DIM);
#pragma unroll
    for (int i = 0; i < 16; i++) {
        float4 vv = row[i];
        dst[2 * i] = __halves2half2(__float2half_rn(vv.x), __float2half_rn(vv.y));
        dst[2 * i + 1] = __halves2half2(__float2half_rn(vv.z), __float2half_rn(vv.w));
    }
}

// ---------------- main: HMMA distance GEMM + approx argmin ----------------
__global__ void __launch_bounds__(256, 2) vq_mma_kernel() {
    extern __shared__ __align__(16) char dsm[];
    __shared__ float s_b[2][TILE_M], s_b2[2][TILE_M];
    __shared__ int s_i[2][TILE_M];

    const int tid = threadIdx.x;
    const int lane = tid & 31, wid = tid >> 5;
    const int wm = wid & 3, wn = wid >> 2;  // 4 M-stripes x 2 N-stripes
    const uint32_t sb = smem_u32(dsm);

    // A tile: 128 rows x 64 halfs (128B) -> padded 144B rows
    {
        const uint4* asrc =
            reinterpret_cast<const uint4*>(g_zh + (size_t)blockIdx.x * TILE_M * DIM);
#pragma unroll
        for (int i = 0; i < 4; i++) {
            int ch = tid + i * 256;          // 1024 chunks of 16B
            int r = ch >> 3, c = ch & 7;
            cpa16(sb + SM_A + r * KP_BYTES + c * 16, asrc + ch);
        }
    }
    auto loadB = [&](int t) {
        uint32_t Bs = sb + SM_B + (t & 1) * SM_BSTRIDE;
        const uint4* bsrc =
            reinterpret_cast<const uint4*>(g_eh + (size_t)t * TILE_N * DIM);
#pragma unroll
        for (int i = 0; i < 2; i++) {
            int ch = tid + i * 256;          // 512 chunks
            int r = ch >> 3, c = ch & 7;
            cpa16(Bs + r * KP_BYTES + c * 16, bsrc + ch);
        }
        if (tid < 16)
            cpa16(sb + SM_ESQ + (t & 1) * 256 + tid * 16,
                  reinterpret_cast<const uint4*>(g_esq + t * TILE_N) + tid);
    };
    loadB(0);
    CP_COMMIT();

    float best[4], best2[4];
    int bi[4];
#pragma unroll
    for (int s = 0; s < 4; s++) { best[s] = 3.4e38f; best2[s] = 3.4e38f; bi[s] = 0; }

    const uint32_t a_row = wm * 32 + (lane & 15);
    const uint32_t a_koff = (lane >> 4) * 8;
    const uint32_t b_row0 = wn * 32 + ((lane >> 4) * 8) + (lane & 7);
    const uint32_t b_koff = ((lane >> 3) & 1) * 8;
    const int nq = (lane & 3) * 2;

    for (int t = 0; t < NT; t++) {
        if (t + 1 < NT) { loadB(t + 1); CP_COMMIT(); CP_WAIT(1); }
        else           { CP_WAIT(0); }
        __syncthreads();

        float acc[2][4][4];
#pragma unroll
        for (int mf = 0; mf < 2; mf++)
#pragma unroll
            for (int nf = 0; nf < 4; nf++)
#pragma unroll
                for (int e = 0; e < 4; e++) acc[mf][nf][e] = 0.f;

        const uint32_t Bs = sb + SM_B + (t & 1) * SM_BSTRIDE;
#pragma unroll
        for (int ks = 0; ks < DIM / 16; ks++) {
            uint32_t a[2][4];
#pragma unroll
            for (int mf = 0; mf < 2; mf++)
                ldsm4(a[mf][0], a[mf][1], a[mf][2], a[mf][3],
                      sb + SM_A + (a_row + mf * 16) * KP_BYTES +
                          (ks * 16 + a_koff) * 2);
            uint32_t b[4][2];
#pragma unroll
            for (int nh = 0; nh < 2; nh++)
                ldsm4(b[2 * nh][0], b[2 * nh][1], b[2 * nh + 1][0], b[2 * nh + 1][1],
                      Bs + (b_row0 + nh * 16) * KP_BYTES + (ks * 16 + b_koff) * 2);
#pragma unroll
            for (int mf = 0; mf < 2; mf++)
#pragma unroll
                for (int nf = 0; nf < 4; nf++)
                    mma16816(acc[mf][nf], a[mf], b[nf][0], b[nf][1]);
        }

        // epilogue: scores per row-slot, fast tree-min skip path
        const float* esq =
            reinterpret_cast<const float*>(dsm + SM_ESQ + (t & 1) * 256);
        float sc[4][8];  // [slot = mf*2+h][nf*2 + colpair]
#pragma unroll
        for (int mf = 0; mf < 2; mf++) {
#pragma unroll
            for (int nf = 0; nf < 4; nf++) {
                const int n0 = wn * 32 + nf * 8 + nq;
                const float e0 = esq[n0], e1 = esq[n0 + 1];
#pragma unroll
                for (int h = 0; h < 2; h++) {
                    sc[mf * 2 + h][nf * 2 + 0] = fmaf(-2.f, acc[mf][nf][2 * h], e0);
                    sc[mf * 2 + h][nf * 2 + 1] = fmaf(-2.f, acc[mf][nf][2 * h + 1], e1);
                }
            }
        }
#pragma unroll
        for (int s = 0; s < 4; s++) {
            float m01 = fminf(sc[s][0], sc[s][1]);
            float m23 = fminf(sc[s][2], sc[s][3]);
            float m45 = fminf(sc[s][4], sc[s][5]);
            float m67 = fminf(sc[s][6], sc[s][7]);
            float tmin = fminf(fminf(m01, m23), fminf(m45, m67));
            if (tmin < best2[s]) {
#pragma unroll
                for (int k = 0; k < 8; k++) {
                    float v = sc[s][k];
                    int idx = t * TILE_N + wn * 32 + (k >> 1) * 8 + nq + (k & 1);
                    if (v < best[s]) { best2[s] = best[s]; best[s] = v; bi[s] = idx; }
                    else if (v < best2[s]) best2[s] = v;
                }
            }
        }
        __syncthreads();  // protect B stage reuse
    }

    // quad reduce (lanes sharing the same rows: xor 1, 2)
#pragma unroll
    for (int o = 1; o < 4; o <<= 1) {
#pragma unroll
        for (int s = 0; s < 4; s++) {
            float ob = __shfl_xor_sync(0xffffffffu, best[s], o);
            float ob2 = __shfl_xor_sync(0xffffffffu, best2[s], o);
            int obi = __shfl_xor_sync(0xffffffffu, bi[s], o);
            if (ob < best[s] || (ob == best[s] && obi < bi[s])) {
                best2[s] = fminf(best[s], ob2);
                best[s] = ob;
                bi[s] = obi;
            } else {
                best2[s] = fminf(best2[s], ob);
            }
        }
    }
    if ((lane & 3) == 0) {
#pragma unroll
        for (int s = 0; s < 4; s++) {
            int row = wm * 32 + (s >> 1) * 16 + (lane >> 2) + (s & 1) * 8;
            s_b[wn][row] = best[s];
            s_b2[wn][row] = best2[s];
            s_i[wn][row] = bi[s];
        }
    }
    __syncthreads();
    if (tid < TILE_M) {
        float b0v = s_b[0][tid], b1v = s_b[1][tid];
        float q0 = s_b2[0][tid], q1 = s_b2[1][tid];
        int i0 = s_i[0][tid], i1 = s_i[1][tid];
        float nb, nb2;
        int ni;
        if (b0v < b1v || (b0v == b1v && i0 < i1)) {
            nb = b0v; ni = i0; nb2 = fminf(q0, b1v);
        } else {
            nb = b1v; ni = i1; nb2 = fminf(q1, b0v);
        }
        const int v = blockIdx.x * TILE_M + tid;
        g_bidx[v] = ni;
        if (nb2 - nb < TAU) {
            int p = atomicAdd(&g_count, 1);
            g_list[p] = v;
        }
    }
}

// ---------------- exact fp32 fixup: block-per-voxel ----------------
__global__ void __launch_bounds__(256) fixup_kernel(const float* __restrict__ z,
                                                    const float* __restrict__ emb) {
    __shared__ float s_z[DIM];
    __shared__ float s_v[256];
    __shared__ int s_ix[256];
    const int tid = threadIdx.x;
    const int nflag = g_count;

    for (int i = blockIdx.x; i < nflag; i += gridDim.x) {
        const int v = g_list[i];
        if (tid < 16)
            reinterpret_cast<float4*>(s_z)[tid] =
                reinterpret_cast<const float4*>(z + (size_t)v * DIM)[tid];
        __syncthreads();

        float lb = 3.4e38f;
        int li = 0;
#pragma unroll 2
        for (int c = tid; c < NC; c += 256) {
            const float4* ep = reinterpret_cast<const float4*>(emb + (size_t)c * DIM);
            float d0 = 0.f, d1 = 0.f, d2 = 0.f, d3 = 0.f;
#pragma unroll
            for (int j = 0; j < 16; j += 4) {
                float4 e0 = ep[j], e1 = ep[j + 1], e2 = ep[j + 2], e3 = ep[j + 3];
                d0 = fmaf(s_z[4 * j + 0], e0.x, d0);
                d0 = fmaf(s_z[4 * j + 1], e0.y, d0);
                d0 = fmaf(s_z[4 * j + 2], e0.z, d0);
                d0 = fmaf(s_z[4 * j + 3], e0.w, d0);
                d1 = fmaf(s_z[4 * j + 4], e1.x, d1);
                d1 = fmaf(s_z[4 * j + 5], e1.y, d1);
                d1 = fmaf(s_z[4 * j + 6], e1.z, d1);
                d1 = fmaf(s_z[4 * j + 7], e1.w, d1);
                d2 = fmaf(s_z[4 * j + 8], e2.x, d2);
                d2 = fmaf(s_z[4 * j + 9], e2.y, d2);
                d2 = fmaf(s_z[4 * j + 10], e2.z, d2);
                d2 = fmaf(s_z[4 * j + 11], e2.w, d2);
                d3 = fmaf(s_z[4 * j + 12], e3.x, d3);
                d3 = fmaf(s_z[4 * j + 13], e3.y, d3);
                d3 = fmaf(s_z[4 * j + 14], e3.z, d3);
                d3 = fmaf(s_z[4 * j + 15], e3.w, d3);
            }
            float dot = (d0 + d1) + (d2 + d3);
            float s = fmaf(-2.f, dot, g_esq[c]);
            if (s < lb) { lb = s; li = c; }  // ascending c => lowest index on tie
        }
        s_v[tid] = lb;
        s_ix[tid] = li;
        __syncthreads();
#pragma unroll
        for (int o = 128; o > 0; o >>= 1) {
            if (tid < o) {
                float ov = s_v[tid + o];
                int oi = s_ix[tid + o];
                if (ov < s_v[tid] || (ov == s_v[tid] && oi < s_ix[tid])) {
                    s_v[tid] = ov;
                    s_ix[tid] = oi;
                }
            }
            __syncthreads();
        }
        if (tid == 0) g_bidx[v] = s_ix[0];
        __syncthreads();  // s_z reuse next iteration
    }
}

// ---------------- gather / straight-through / loss partials ----------------
__global__ void __launch_bounds__(128) quant_kernel(const float* __restrict__ z,
                                                    const float* __restrict__ emb,
                                                    float* __restrict__ out) {
    __shared__ float s_red[128];
    const int v = blockIdx.x * 128 + threadIdx.x;
    const int idx = g_bidx[v];

    const float4* zp = reinterpret_cast<const float4*>(z + (size_t)v * DIM);
    const float4* qp = reinterpret_cast<const float4*>(emb + (size_t)idx * DIM);
    float4* qo = reinterpret_cast<float4*>(out + (size_t)v * DIM);
    float lsum = 0.f;
#pragma unroll
    for (int i = 0; i < 16; i++) {
        float4 zv = zp[i], q = qp[i];
        float dx = q.x - zv.x, dy = q.y - zv.y, dz = q.z - zv.z, dw = q.w - zv.w;
        qo[i] = make_float4(zv.x + dx, zv.y + dy, zv.z + dz, zv.w + dw);
        lsum += dx * dx + dy * dy + dz * dz + dw * dw;
    }
    out[OFF_IDX + v] = (float)idx;

    s_red[threadIdx.x] = lsum;
    __syncthreads();
#pragma unroll
    for (int o = 64; o > 0; o >>= 1) {
        if (threadIdx.x < o) s_red[threadIdx.x] += s_red[threadIdx.x + o];
        __syncthreads();
    }
    if (threadIdx.x == 0) g_partial[blockIdx.x] = s_red[0];
}

// ---------------- final loss reduction ----------------
__global__ void final_kernel(float* __restrict__ out) {
    __shared__ float s[M_BLOCKS];
    int tid = threadIdx.x;
    s[tid] = g_partial[tid];
    __syncthreads();
#pragma unroll
    for (int o = M_BLOCKS / 2; o > 0; o >>= 1) {
        if (tid < o) s[tid] += s[tid + o];
        __syncthreads();
    }
    if (tid == 0) {
        float loss = s[0] / (float)Q_ELEMS;
        out[OFF_VQ] = loss;
        out[OFF_COMMIT] = loss;
    }
}

// ---------------- launch ----------------
extern "C" void kernel_launch(void* const* d_in, const int* in_sizes, int n_in,
                              void* d_out, int out_size) {
    const float* z = (const float*)d_in[0];
    const float* emb = (const float*)d_in[1];
    if (n_in >= 2 && in_sizes[0] < in_sizes[1]) {
        const float* t = z; z = emb; emb = t;
    }
    float* out = (float*)d_out;

    cudaFuncSetAttribute(vq_mma_kernel,
                         cudaFuncAttributeMaxDynamicSharedMemorySize, DYN_SMEM);

    prep_emb_kernel<<<(NC + 255) / 256, 256>>>(emb);
    prep_z_kernel<<<(NV + 255) / 256, 256>>>(z);
    vq_mma_kernel<<<M_BLOCKS, 256, DYN_SMEM>>>();
    fixup_kernel<<<1024, 256>>>(z, emb);
    quant_kernel<<<NV / 128, 128>>>(z, emb, out);
    final_kernel<<<1, M_BLOCKS>>>(out);
}

// round 6
// speedup vs baseline: 1.7886x; 1.7886x over previous
#include <cuda_runtime.h>
#include <cuda_fp16.h>
#include <cstdint>

// ---------------- problem constants ----------------
#define NV 32768
#define NC 8192
#define DIM 64
#define Q_ELEMS (NV * DIM)
#define OFF_VQ Q_ELEMS
#define OFF_COMMIT (Q_ELEMS + 1)
#define OFF_IDX (Q_ELEMS + 2)

#define KP_BYTES 144    // padded smem row stride: 128B data + 16B pad (conflict-free ldsm)
#define TILE_M 128
#define TILE_N 64
#define NT (NC / TILE_N)        // 128 tiles
#define M_BLOCKS (NV / TILE_M)  // 256 CTAs
#define TAU 0.35f               // covers rigorous fp16 score-error bound (~0.31)

// dynamic smem: A 128*144=18432 | B stage0 64*144=9216 | B stage1 | esq 2*256
#define SM_A 0
#define SM_B 18432
#define SM_BSTRIDE 9216
#define SM_ESQ 36864
#define DYN_SMEM 37632

#define FB 8  // flagged voxels per fixup block-iteration

// ---------------- device scratch ----------------
__device__ __align__(16) __half g_zh[NV * DIM];    // 4 MB
__device__ __align__(16) __half g_eh[NC * DIM];    // 1 MB
__device__ __align__(16) float4 g_eT4[16 * NC];    // 2 MB, transposed codebook
__device__ __align__(16) float g_esq[NC];
__device__ int g_bidx[NV];
__device__ int g_list[NV];
__device__ int g_count;
__device__ float g_partial[M_BLOCKS];

// ---------------- PTX helpers (baseline sm_80+ features only) ----------------
__device__ __forceinline__ uint32_t smem_u32(const void* p) {
    uint32_t a;
    asm("{ .reg .u64 t; cvta.to.shared.u64 t, %1; cvt.u32.u64 %0, t; }" : "=r"(a) : "l"(p));
    return a;
}
__device__ __forceinline__ void cpa16(uint32_t dst, const void* src) {
    asm volatile("cp.async.cg.shared.global [%0], [%1], 16;" :: "r"(dst), "l"(src));
}
#define CP_COMMIT() asm volatile("cp.async.commit_group;" ::: "memory")
#define CP_WAIT(n) asm volatile("cp.async.wait_group %0;" :: "n"(n) : "memory")

__device__ __forceinline__ void ldsm4(uint32_t& r0, uint32_t& r1, uint32_t& r2,
                                      uint32_t& r3, uint32_t addr) {
    asm volatile("ldmatrix.sync.aligned.m8n8.x4.shared.b16 {%0,%1,%2,%3}, [%4];"
                 : "=r"(r0), "=r"(r1), "=r"(r2), "=r"(r3) : "r"(addr));
}
__device__ __forceinline__ void mma16816(float* c, const uint32_t* a, uint32_t b0,
                                         uint32_t b1) {
    asm volatile(
        "mma.sync.aligned.m16n8k16.row.col.f32.f16.f16.f32 "
        "{%0,%1,%2,%3}, {%4,%5,%6,%7}, {%8,%9}, {%0,%1,%2,%3};"
        : "+f"(c[0]), "+f"(c[1]), "+f"(c[2]), "+f"(c[3])
        : "r"(a[0]), "r"(a[1]), "r"(a[2]), "r"(a[3]), "r"(b0), "r"(b1));
}

// ---------------- prep: codebook -> fp16 + transposed fp32 + exact esq ----------------
__global__ void prep_emb_kernel(const float* __restrict__ emb) {
    int c = blockIdx.x * blockDim.x + threadIdx.x;
    if (c == 0) g_count = 0;
    if (c >= NC) return;
    const float4* row = reinterpret_cast<const float4*>(emb + (size_t)c * DIM);
    __half2* dst = reinterpret_cast<__half2*>(g_eh + (size_t)c * DIM);
    float s = 0.f;
#pragma unroll
    for (int i = 0; i < 16; i++) {
        float4 v = row[i];
        s += v.x * v.x + v.y * v.y + v.z * v.z + v.w * v.w;
        dst[2 * i] = __halves2half2(__float2half_rn(v.x), __float2half_rn(v.y));
        dst[2 * i + 1] = __halves2half2(__float2half_rn(v.z), __float2half_rn(v.w));
        g_eT4[i * NC + c] = v;  // transposed layout for coalesced fixup
    }
    g_esq[c] = s;
}

// ---------------- prep: z -> fp16 ----------------
__global__ void prep_z_kernel(const float* __restrict__ z) {
    int v = blockIdx.x * blockDim.x + threadIdx.x;
    if (v >= NV) return;
    const float4* row = reinterpret_cast<const float4*>(z + (size_t)v * DIM);
    __half2* dst = reinterpret_cast<__half2*>(g_zh + (size_t)v * DIM);
#pragma unroll
    for (int i = 0; i < 16; i++) {
        float4 vv = row[i];
        dst[2 * i] = __halves2half2(__float2half_rn(vv.x), __float2half_rn(vv.y));
        dst[2 * i + 1] = __halves2half2(__float2half_rn(vv.z), __float2half_rn(vv.w));
    }
}

// ---------------- main: HMMA distance GEMM + approx argmin ----------------
__global__ void __launch_bounds__(256, 2) vq_mma_kernel() {
    extern __shared__ __align__(16) char dsm[];
    __shared__ float s_b[2][TILE_M], s_b2[2][TILE_M];
    __shared__ int s_i[2][TILE_M];

    const int tid = threadIdx.x;
    const int lane = tid & 31, wid = tid >> 5;
    const int wm = wid & 3, wn = wid >> 2;  // 4 M-stripes x 2 N-stripes
    const uint32_t sb = smem_u32(dsm);

    // A tile: 128 rows x 64 halfs (128B) -> padded 144B rows
    {
        const uint4* asrc =
            reinterpret_cast<const uint4*>(g_zh + (size_t)blockIdx.x * TILE_M * DIM);
#pragma unroll
        for (int i = 0; i < 4; i++) {
            int ch = tid + i * 256;          // 1024 chunks of 16B
            int r = ch >> 3, c = ch & 7;
            cpa16(sb + SM_A + r * KP_BYTES + c * 16, asrc + ch);
        }
    }
    auto loadB = [&](int t) {
        uint32_t Bs = sb + SM_B + (t & 1) * SM_BSTRIDE;
        const uint4* bsrc =
            reinterpret_cast<const uint4*>(g_eh + (size_t)t * TILE_N * DIM);
#pragma unroll
        for (int i = 0; i < 2; i++) {
            int ch = tid + i * 256;          // 512 chunks
            int r = ch >> 3, c = ch & 7;
            cpa16(Bs + r * KP_BYTES + c * 16, bsrc + ch);
        }
        if (tid < 16)
            cpa16(sb + SM_ESQ + (t & 1) * 256 + tid * 16,
                  reinterpret_cast<const uint4*>(g_esq + t * TILE_N) + tid);
    };
    loadB(0);
    CP_COMMIT();

    float best[4], best2[4];
    int bi[4];
#pragma unroll
    for (int s = 0; s < 4; s++) { best[s] = 3.4e38f; best2[s] = 3.4e38f; bi[s] = 0; }

    const uint32_t a_row = wm * 32 + (lane & 15);
    const uint32_t a_koff = (lane >> 4) * 8;
    const uint32_t b_row0 = wn * 32 + ((lane >> 4) * 8) + (lane & 7);
    const uint32_t b_koff = ((lane >> 3) & 1) * 8;
    const int nq = (lane & 3) * 2;

    for (int t = 0; t < NT; t++) {
        if (t + 1 < NT) { loadB(t + 1); CP_COMMIT(); CP_WAIT(1); }
        else           { CP_WAIT(0); }
        __syncthreads();

        float acc[2][4][4];
#pragma unroll
        for (int mf = 0; mf < 2; mf++)
#pragma unroll
            for (int nf = 0; nf < 4; nf++)
#pragma unroll
                for (int e = 0; e < 4; e++) acc[mf][nf][e] = 0.f;

        const uint32_t Bs = sb + SM_B + (t & 1) * SM_BSTRIDE;
#pragma unroll
        for (int ks = 0; ks < DIM / 16; ks++) {
            uint32_t a[2][4];
#pragma unroll
            for (int mf = 0; mf < 2; mf++)
                ldsm4(a[mf][0], a[mf][1], a[mf][2], a[mf][3],
                      sb + SM_A + (a_row + mf * 16) * KP_BYTES +
                          (ks * 16 + a_koff) * 2);
            uint32_t b[4][2];
#pragma unroll
            for (int nh = 0; nh < 2; nh++)
                ldsm4(b[2 * nh][0], b[2 * nh][1], b[2 * nh + 1][0], b[2 * nh + 1][1],
                      Bs + (b_row0 + nh * 16) * KP_BYTES + (ks * 16 + b_koff) * 2);
#pragma unroll
            for (int mf = 0; mf < 2; mf++)
#pragma unroll
                for (int nf = 0; nf < 4; nf++)
                    mma16816(acc[mf][nf], a[mf], b[nf][0], b[nf][1]);
        }

        // epilogue: scores per row-slot, fast tree-min skip path
        const float* esq =
            reinterpret_cast<const float*>(dsm + SM_ESQ + (t & 1) * 256);
        float sc[4][8];  // [slot = mf*2+h][nf*2 + colpair]
#pragma unroll
        for (int mf = 0; mf < 2; mf++) {
#pragma unroll
            for (int nf = 0; nf < 4; nf++) {
                const int n0 = wn * 32 + nf * 8 + nq;
                const float e0 = esq[n0], e1 = esq[n0 + 1];
#pragma unroll
                for (int h = 0; h < 2; h++) {
                    sc[mf * 2 + h][nf * 2 + 0] = fmaf(-2.f, acc[mf][nf][2 * h], e0);
                    sc[mf * 2 + h][nf * 2 + 1] = fmaf(-2.f, acc[mf][nf][2 * h + 1], e1);
                }
            }
        }
#pragma unroll
        for (int s = 0; s < 4; s++) {
            float m01 = fminf(sc[s][0], sc[s][1]);
            float m23 = fminf(sc[s][2], sc[s][3]);
            float m45 = fminf(sc[s][4], sc[s][5]);
            float m67 = fminf(sc[s][6], sc[s][7]);
            float tmin = fminf(fminf(m01, m23), fminf(m45, m67));
            if (tmin < best2[s]) {
#pragma unroll
                for (int k = 0; k < 8; k++) {
                    float v = sc[s][k];
                    int idx = t * TILE_N + wn * 32 + (k >> 1) * 8 + nq + (k & 1);
                    if (v < best[s]) { best2[s] = best[s]; best[s] = v; bi[s] = idx; }
                    else if (v < best2[s]) best2[s] = v;
                }
            }
        }
        __syncthreads();  // protect B stage reuse
    }

    // quad reduce (lanes sharing the same rows: xor 1, 2)
#pragma unroll
    for (int o = 1; o < 4; o <<= 1) {
#pragma unroll
        for (int s = 0; s < 4; s++) {
            float ob = __shfl_xor_sync(0xffffffffu, best[s], o);
            float ob2 = __shfl_xor_sync(0xffffffffu, best2[s], o);
            int obi = __shfl_xor_sync(0xffffffffu, bi[s], o);
            if (ob < best[s] || (ob == best[s] && obi < bi[s])) {
                best2[s] = fminf(best[s], ob2);
                best[s] = ob;
                bi[s] = obi;
            } else {
                best2[s] = fminf(best2[s], ob);
            }
        }
    }
    if ((lane & 3) == 0) {
#pragma unroll
        for (int s = 0; s < 4; s++) {
            int row = wm * 32 + (s >> 1) * 16 + (lane >> 2) + (s & 1) * 8;
            s_b[wn][row] = best[s];
            s_b2[wn][row] = best2[s];
            s_i[wn][row] = bi[s];
        }
    }
    __syncthreads();
    if (tid < TILE_M) {
        float b0v = s_b[0][tid], b1v = s_b[1][tid];
        float q0 = s_b2[0][tid], q1 = s_b2[1][tid];
        int i0 = s_i[0][tid], i1 = s_i[1][tid];
        float nb, nb2;
        int ni;
        if (b0v < b1v || (b0v == b1v && i0 < i1)) {
            nb = b0v; ni = i0; nb2 = fminf(q0, b1v);
        } else {
            nb = b1v; ni = i1; nb2 = fminf(q1, b0v);
        }
        const int v = blockIdx.x * TILE_M + tid;
        g_bidx[v] = ni;
        if (nb2 - nb < TAU) {
            int p = atomicAdd(&g_count, 1);
            g_list[p] = v;
        }
    }
}

// ---------------- exact fp32 fixup: 8 voxels/block, coalesced transposed codebook ----------------
__global__ void __launch_bounds__(256) fixup_kernel(const float* __restrict__ z) {
    __shared__ __align__(16) float4 s_z4[FB][16];
    __shared__ float s_wv[8][FB];
    __shared__ int s_wi[8][FB];
    const int tid = threadIdx.x, lane = tid & 31, wid = tid >> 5;
    const int nflag = g_count;
    const int nbatch = (nflag + FB - 1) / FB;

    for (int b = blockIdx.x; b < nbatch; b += gridDim.x) {
        const int base = b * FB;
        const int nb = min(FB, nflag - base);
        if (tid < FB * 16) {
            int k = tid >> 4, j = tid & 15;
            int src = base + (k < nb ? k : 0);  // clamp tail (harmless duplicate)
            s_z4[k][j] =
                reinterpret_cast<const float4*>(z + (size_t)g_list[src] * DIM)[j];
        }
        __syncthreads();

        float lb[FB];
        int li[FB];
#pragma unroll
        for (int k = 0; k < FB; k++) { lb[k] = 3.4e38f; li[k] = 0; }

        for (int chunk = 0; chunk < NC / 1024; chunk++) {
            const int cbase = chunk * 1024;
            float acc[4][FB];
#pragma unroll
            for (int q = 0; q < 4; q++)
#pragma unroll
                for (int k = 0; k < FB; k++) acc[q][k] = 0.f;

#pragma unroll
            for (int jg = 0; jg < 16; jg++) {
                float4 zj[FB];
#pragma unroll
                for (int k = 0; k < FB; k++) zj[k] = s_z4[k][jg];  // smem broadcast
#pragma unroll
                for (int q = 0; q < 4; q++) {
                    float4 e = g_eT4[jg * NC + cbase + q * 256 + tid];  // coalesced
#pragma unroll
                    for (int k = 0; k < FB; k++) {
                        acc[q][k] = fmaf(zj[k].x, e.x, acc[q][k]);
                        acc[q][k] = fmaf(zj[k].y, e.y, acc[q][k]);
                        acc[q][k] = fmaf(zj[k].z, e.z, acc[q][k]);
                        acc[q][k] = fmaf(zj[k].w, e.w, acc[q][k]);
                    }
                }
            }
#pragma unroll
            for (int q = 0; q < 4; q++) {
                const int c = cbase + q * 256 + tid;  // ascending within thread
                const float esq = g_esq[c];
#pragma unroll
                for (int k = 0; k < FB; k++) {
                    float s = fmaf(-2.f, acc[q][k], esq);
                    if (s < lb[k]) { lb[k] = s; li[k] = c; }
                }
            }
        }

        // warp reduce with index tie-break
#pragma unroll
        for (int o = 16; o > 0; o >>= 1) {
#pragma unroll
            for (int k = 0; k < FB; k++) {
                float os = __shfl_down_sync(0xffffffffu, lb[k], o);
                int oi = __shfl_down_sync(0xffffffffu, li[k], o);
                if (os < lb[k] || (os == lb[k] && oi < li[k])) { lb[k] = os; li[k] = oi; }
            }
        }
        if (lane == 0) {
#pragma unroll
            for (int k = 0; k < FB; k++) { s_wv[wid][k] = lb[k]; s_wi[wid][k] = li[k]; }
        }
        __syncthreads();
        if (tid < nb) {
            float bv = s_wv[0][tid];
            int bix = s_wi[0][tid];
#pragma unroll
            for (int w = 1; w < 8; w++) {
                float ov = s_wv[w][tid];
                int oi = s_wi[w][tid];
                if (ov < bv || (ov == bv && oi < bix)) { bv = ov; bix = oi; }
            }
            g_bidx[g_list[base + tid]] = bix;
        }
        __syncthreads();
    }
}

// ---------------- gather / straight-through / loss partials ----------------
__global__ void __launch_bounds__(128) quant_kernel(const float* __restrict__ z,
                                                    const float* __restrict__ emb,
                                                    float* __restrict__ out) {
    __shared__ float s_red[128];
    const int v = blockIdx.x * 128 + threadIdx.x;
    const int idx = g_bidx[v];

    const float4* zp = reinterpret_cast<const float4*>(z + (size_t)v * DIM);
    const float4* qp = reinterpret_cast<const float4*>(emb + (size_t)idx * DIM);
    float4* qo = reinterpret_cast<float4*>(out + (size_t)v * DIM);
    float lsum = 0.f;
#pragma unroll
    for (int i = 0; i < 16; i++) {
        float4 zv = zp[i], q = qp[i];
        float dx = q.x - zv.x, dy = q.y - zv.y, dz = q.z - zv.z, dw = q.w - zv.w;
        qo[i] = make_float4(zv.x + dx, zv.y + dy, zv.z + dz, zv.w + dw);
        lsum += dx * dx + dy * dy + dz * dz + dw * dw;
    }
    out[OFF_IDX + v] = (float)idx;

    s_red[threadIdx.x] = lsum;
    __syncthreads();
#pragma unroll
    for (int o = 64; o > 0; o >>= 1) {
        if (threadIdx.x < o) s_red[threadIdx.x] += s_red[threadIdx.x + o];
        __syncthreads();
    }
    if (threadIdx.x == 0) g_partial[blockIdx.x] = s_red[0];
}

// ---------------- final loss reduction ----------------
__global__ void final_kernel(float* __restrict__ out) {
    __shared__ float s[M_BLOCKS];
    int tid = threadIdx.x;
    s[tid] = g_partial[tid];
    __syncthreads();
#pragma unroll
    for (int o = M_BLOCKS / 2; o > 0; o >>= 1) {
        if (tid < o) s[tid] += s[tid + o];
        __syncthreads();
    }
    if (tid == 0) {
        float loss = s[0] / (float)Q_ELEMS;
        out[OFF_VQ] = loss;
        out[OFF_COMMIT] = loss;
    }
}

// ---------------- launch ----------------
extern "C" void kernel_launch(void* const* d_in, const int* in_sizes, int n_in,
                              void* d_out, int out_size) {
    const float* z = (const float*)d_in[0];
    const float* emb = (const float*)d_in[1];
    if (n_in >= 2 && in_sizes[0] < in_sizes[1]) {
        const float* t = z; z = emb; emb = t;
    }
    float* out = (float*)d_out;

    cudaFuncSetAttribute(vq_mma_kernel,
                         cudaFuncAttributeMaxDynamicSharedMemorySize, DYN_SMEM);

    prep_emb_kernel<<<(NC + 255) / 256, 256>>>(emb);
    prep_z_kernel<<<(NV + 255) / 256, 256>>>(z);
    vq_mma_kernel<<<M_BLOCKS, 256, DYN_SMEM>>>();
    fixup_kernel<<<512, 256>>>(z);
    quant_kernel<<<NV / 128, 128>>>(z, emb, out);
    final_kernel<<<1, M_BLOCKS>>>(out);
}

// round 7
// speedup vs baseline: 3.2853x; 1.8368x over previous
#include <cuda_runtime.h>
#include <cuda_fp16.h>
#include <cstdint>

// ---------------- problem constants ----------------
#define NV 32768
#define NC 8192
#define DIM 64
#define Q_ELEMS (NV * DIM)
#define OFF_VQ Q_ELEMS
#define OFF_COMMIT (Q_ELEMS + 1)
#define OFF_IDX (Q_ELEMS + 2)

#define KP_BYTES 144
#define TILE_M 128
#define TILE_N 64
#define NT (NC / TILE_N)        // 128
#define M_BLOCKS (NV / TILE_M)  // 256
#define TAU 0.35f               // rigorous fp16 score-error cover

#define SM_A 0
#define SM_B 18432
#define SM_BSTRIDE 9216
#define SM_ESQ 36864
#define DYN_SMEM 37632

#define FB 8

// ---------------- device scratch ----------------
__device__ __align__(16) __half g_zh[NV * DIM];
__device__ __align__(16) __half g_eh[NC * DIM];
__device__ __align__(16) float4 g_eT4[16 * NC];
__device__ __align__(16) float g_esq[NC];
__device__ int g_bidx[NV];
__device__ int3 g_pair[NV];   // (voxel, i1, i2)
__device__ int g_full[NV];
__device__ int g_npair;
__device__ int g_nfull;
__device__ float g_partial[M_BLOCKS];

// ---------------- PTX helpers ----------------
__device__ __forceinline__ uint32_t smem_u32(const void* p) {
    uint32_t a;
    asm("{ .reg .u64 t; cvta.to.shared.u64 t, %1; cvt.u32.u64 %0, t; }" : "=r"(a) : "l"(p));
    return a;
}
__device__ __forceinline__ void cpa16(uint32_t dst, const void* src) {
    asm volatile("cp.async.cg.shared.global [%0], [%1], 16;" :: "r"(dst), "l"(src));
}
#define CP_COMMIT() asm volatile("cp.async.commit_group;" ::: "memory")
#define CP_WAIT(n) asm volatile("cp.async.wait_group %0;" :: "n"(n) : "memory")

__device__ __forceinline__ void ldsm4(uint32_t& r0, uint32_t& r1, uint32_t& r2,
                                      uint32_t& r3, uint32_t addr) {
    asm volatile("ldmatrix.sync.aligned.m8n8.x4.shared.b16 {%0,%1,%2,%3}, [%4];"
                 : "=r"(r0), "=r"(r1), "=r"(r2), "=r"(r3) : "r"(addr));
}
__device__ __forceinline__ void mma16816(float* c, const uint32_t* a, uint32_t b0,
                                         uint32_t b1) {
    asm volatile(
        "mma.sync.aligned.m16n8k16.row.col.f32.f16.f16.f32 "
        "{%0,%1,%2,%3}, {%4,%5,%6,%7}, {%8,%9}, {%0,%1,%2,%3};"
        : "+f"(c[0]), "+f"(c[1]), "+f"(c[2]), "+f"(c[3])
        : "r"(a[0]), "r"(a[1]), "r"(a[2]), "r"(a[3]), "r"(b0), "r"(b1));
}

// merge top-3 structure C into A (disjoint index sets; index tie-break)
__device__ __forceinline__ void merge3(float& b1, float& b2, float& b3, int& i1, int& i2,
                                       float c1, float c2, float c3, int j1, int j2) {
    if (c1 < b1 || (c1 == b1 && j1 < i1)) {
        float t; int ti;
        t = b1; b1 = c1; c1 = t; ti = i1; i1 = j1; j1 = ti;
        t = b2; b2 = c2; c2 = t; ti = i2; i2 = j2; j2 = ti;
        t = b3; b3 = c3; c3 = t;
    }
    if (c1 < b2 || (c1 == b2 && j1 < i2)) {
        b3 = fminf(b2, c2);
        b2 = c1; i2 = j1;
    } else {
        b3 = fminf(b3, c1);
    }
}

// ---------------- prep: codebook ----------------
__global__ void prep_emb_kernel(const float* __restrict__ emb) {
    int c = blockIdx.x * blockDim.x + threadIdx.x;
    if (c == 0) { g_npair = 0; g_nfull = 0; }
    if (c >= NC) return;
    const float4* row = reinterpret_cast<const float4*>(emb + (size_t)c * DIM);
    __half2* dst = reinterpret_cast<__half2*>(g_eh + (size_t)c * DIM);
    float s = 0.f;
#pragma unroll
    for (int i = 0; i < 16; i++) {
        float4 v = row[i];
        s += v.x * v.x + v.y * v.y + v.z * v.z + v.w * v.w;
        dst[2 * i] = __halves2half2(__float2half_rn(v.x), __float2half_rn(v.y));
        dst[2 * i + 1] = __halves2half2(__float2half_rn(v.z), __float2half_rn(v.w));
        g_eT4[i * NC + c] = v;
    }
    g_esq[c] = s;
}

// ---------------- prep: z ----------------
__global__ void prep_z_kernel(const float* __restrict__ z) {
    int v = blockIdx.x * blockDim.x + threadIdx.x;
    if (v >= NV) return;
    const float4* row = reinterpret_cast<const float4*>(z + (size_t)v * DIM);
    __half2* dst = reinterpret_cast<__half2*>(g_zh + (size_t)v * DIM);
#pragma unroll
    for (int i = 0; i < 16; i++) {
        float4 vv = row[i];
        dst[2 * i] = __halves2half2(__float2half_rn(vv.x), __float2half_rn(vv.y));
        dst[2 * i + 1] = __halves2half2(__float2half_rn(vv.z), __float2half_rn(vv.w));
    }
}

// ---------------- main: HMMA distance GEMM + top-3 argmin ----------------
__global__ void __launch_bounds__(256, 2) vq_mma_kernel() {
    extern __shared__ __align__(16) char dsm[];
    __shared__ float s_b[2][TILE_M], s_b2[2][TILE_M], s_b3[2][TILE_M];
    __shared__ int s_i[2][TILE_M], s_i2[2][TILE_M];

    const int tid = threadIdx.x;
    const int lane = tid & 31, wid = tid >> 5;
    const int wm = wid & 3, wn = wid >> 2;
    const uint32_t sb = smem_u32(dsm);

    {
        const uint4* asrc =
            reinterpret_cast<const uint4*>(g_zh + (size_t)blockIdx.x * TILE_M * DIM);
#pragma unroll
        for (int i = 0; i < 4; i++) {
            int ch = tid + i * 256;
            int r = ch >> 3, c = ch & 7;
            cpa16(sb + SM_A + r * KP_BYTES + c * 16, asrc + ch);
        }
    }
    auto loadB = [&](int t) {
        uint32_t Bs = sb + SM_B + (t & 1) * SM_BSTRIDE;
        const uint4* bsrc =
            reinterpret_cast<const uint4*>(g_eh + (size_t)t * TILE_N * DIM);
#pragma unroll
        for (int i = 0; i < 2; i++) {
            int ch = tid + i * 256;
            int r = ch >> 3, c = ch & 7;
            cpa16(Bs + r * KP_BYTES + c * 16, bsrc + ch);
        }
        if (tid < 16)
            cpa16(sb + SM_ESQ + (t & 1) * 256 + tid * 16,
                  reinterpret_cast<const uint4*>(g_esq + t * TILE_N) + tid);
    };
    loadB(0);
    CP_COMMIT();

    float b1[4], b2[4], b3[4];
    int i1[4], i2[4];
#pragma unroll
    for (int s = 0; s < 4; s++) {
        b1[s] = 3.4e38f; b2[s] = 3.4e38f; b3[s] = 3.4e38f; i1[s] = 0; i2[s] = 0;
    }

    const uint32_t a_row = wm * 32 + (lane & 15);
    const uint32_t a_koff = (lane >> 4) * 8;
    const uint32_t b_row0 = wn * 32 + ((lane >> 4) * 8) + (lane & 7);
    const uint32_t b_koff = ((lane >> 3) & 1) * 8;
    const int nq = (lane & 3) * 2;

    for (int t = 0; t < NT; t++) {
        if (t + 1 < NT) { loadB(t + 1); CP_COMMIT(); CP_WAIT(1); }
        else           { CP_WAIT(0); }
        __syncthreads();

        float acc[2][4][4];
#pragma unroll
        for (int mf = 0; mf < 2; mf++)
#pragma unroll
            for (int nf = 0; nf < 4; nf++)
#pragma unroll
                for (int e = 0; e < 4; e++) acc[mf][nf][e] = 0.f;

        const uint32_t Bs = sb + SM_B + (t & 1) * SM_BSTRIDE;
#pragma unroll
        for (int ks = 0; ks < DIM / 16; ks++) {
            uint32_t a[2][4];
#pragma unroll
            for (int mf = 0; mf < 2; mf++)
                ldsm4(a[mf][0], a[mf][1], a[mf][2], a[mf][3],
                      sb + SM_A + (a_row + mf * 16) * KP_BYTES +
                          (ks * 16 + a_koff) * 2);
            uint32_t b[4][2];
#pragma unroll
            for (int nh = 0; nh < 2; nh++)
                ldsm4(b[2 * nh][0], b[2 * nh][1], b[2 * nh + 1][0], b[2 * nh + 1][1],
                      Bs + (b_row0 + nh * 16) * KP_BYTES + (ks * 16 + b_koff) * 2);
#pragma unroll
            for (int mf = 0; mf < 2; mf++)
#pragma unroll
                for (int nf = 0; nf < 4; nf++)
                    mma16816(acc[mf][nf], a[mf], b[nf][0], b[nf][1]);
        }

        const float* esq =
            reinterpret_cast<const float*>(dsm + SM_ESQ + (t & 1) * 256);
        float sc[4][8];
#pragma unroll
        for (int mf = 0; mf < 2; mf++) {
#pragma unroll
            for (int nf = 0; nf < 4; nf++) {
                const int n0 = wn * 32 + nf * 8 + nq;
                const float e0 = esq[n0], e1 = esq[n0 + 1];
#pragma unroll
                for (int h = 0; h < 2; h++) {
                    sc[mf * 2 + h][nf * 2 + 0] = fmaf(-2.f, acc[mf][nf][2 * h], e0);
                    sc[mf * 2 + h][nf * 2 + 1] = fmaf(-2.f, acc[mf][nf][2 * h + 1], e1);
                }
            }
        }
#pragma unroll
        for (int s = 0; s < 4; s++) {
            float m01 = fminf(sc[s][0], sc[s][1]);
            float m23 = fminf(sc[s][2], sc[s][3]);
            float m45 = fminf(sc[s][4], sc[s][5]);
            float m67 = fminf(sc[s][6], sc[s][7]);
            float tmin = fminf(fminf(m01, m23), fminf(m45, m67));
            if (tmin < b3[s]) {
#pragma unroll
                for (int k = 0; k < 8; k++) {
                    float v = sc[s][k];
                    int idx = t * TILE_N + wn * 32 + (k >> 1) * 8 + nq + (k & 1);
                    if (v < b1[s]) {
                        b3[s] = b2[s]; b2[s] = b1[s]; i2[s] = i1[s];
                        b1[s] = v; i1[s] = idx;
                    } else if (v < b2[s]) {
                        b3[s] = b2[s]; b2[s] = v; i2[s] = idx;
                    } else if (v < b3[s]) {
                        b3[s] = v;
                    }
                }
            }
        }
        __syncthreads();
    }

    // quad merge (lanes sharing rows: xor 1, 2)
#pragma unroll
    for (int o = 1; o < 4; o <<= 1) {
#pragma unroll
        for (int s = 0; s < 4; s++) {
            float c1 = __shfl_xor_sync(0xffffffffu, b1[s], o);
            float c2 = __shfl_xor_sync(0xffffffffu, b2[s], o);
            float c3 = __shfl_xor_sync(0xffffffffu, b3[s], o);
            int j1 = __shfl_xor_sync(0xffffffffu, i1[s], o);
            int j2 = __shfl_xor_sync(0xffffffffu, i2[s], o);
            merge3(b1[s], b2[s], b3[s], i1[s], i2[s], c1, c2, c3, j1, j2);
        }
    }
    if ((lane & 3) == 0) {
#pragma unroll
        for (int s = 0; s < 4; s++) {
            int row = wm * 32 + (s >> 1) * 16 + (lane >> 2) + (s & 1) * 8;
            s_b[wn][row] = b1[s];
            s_b2[wn][row] = b2[s];
            s_b3[wn][row] = b3[s];
            s_i[wn][row] = i1[s];
            s_i2[wn][row] = i2[s];
        }
    }
    __syncthreads();
    if (tid < TILE_M) {
        float B1 = s_b[0][tid], B2 = s_b2[0][tid], B3 = s_b3[0][tid];
        int I1 = s_i[0][tid], I2 = s_i2[0][tid];
        merge3(B1, B2, B3, I1, I2,
               s_b[1][tid], s_b2[1][tid], s_b3[1][tid], s_i[1][tid], s_i2[1][tid]);
        const int v = blockIdx.x * TILE_M + tid;
        if (B2 - B1 >= TAU) {
            g_bidx[v] = I1;                       // provably unambiguous
        } else if (B3 - B1 >= TAU) {
            int p = atomicAdd(&g_npair, 1);       // exactly two candidates
            g_pair[p] = make_int3(v, I1, I2);
        } else {
            int p = atomicAdd(&g_nfull, 1);       // rare: full rescan
            g_full[p] = v;
        }
    }
}

// ---------------- pair fixup: 2 exact fp32 distances per flagged voxel ----------------
__global__ void __launch_bounds__(256) pair_fixup_kernel(const float* __restrict__ z,
                                                         const float* __restrict__ emb) {
    const int n = g_npair;
    for (int i = blockIdx.x * blockDim.x + threadIdx.x; i < n;
         i += gridDim.x * blockDim.x) {
        int3 p = g_pair[i];
        const float4* zp = reinterpret_cast<const float4*>(z + (size_t)p.x * DIM);
        const float4* e1 = reinterpret_cast<const float4*>(emb + (size_t)p.y * DIM);
        const float4* e2 = reinterpret_cast<const float4*>(emb + (size_t)p.z * DIM);
        float d1a = 0.f, d1b = 0.f, d2a = 0.f, d2b = 0.f;
#pragma unroll
        for (int j = 0; j < 16; j += 2) {
            float4 zv0 = zp[j], zv1 = zp[j + 1];
            float4 ea0 = e1[j], ea1 = e1[j + 1];
            float4 eb0 = e2[j], eb1 = e2[j + 1];
            d1a = fmaf(zv0.x, ea0.x, d1a); d1a = fmaf(zv0.y, ea0.y, d1a);
            d1a = fmaf(zv0.z, ea0.z, d1a); d1a = fmaf(zv0.w, ea0.w, d1a);
            d1b = fmaf(zv1.x, ea1.x, d1b); d1b = fmaf(zv1.y, ea1.y, d1b);
            d1b = fmaf(zv1.z, ea1.z, d1b); d1b = fmaf(zv1.w, ea1.w, d1b);
            d2a = fmaf(zv0.x, eb0.x, d2a); d2a = fmaf(zv0.y, eb0.y, d2a);
            d2a = fmaf(zv0.z, eb0.z, d2a); d2a = fmaf(zv0.w, eb0.w, d2a);
            d2b = fmaf(zv1.x, eb1.x, d2b); d2b = fmaf(zv1.y, eb1.y, d2b);
            d2b = fmaf(zv1.z, eb1.z, d2b); d2b = fmaf(zv1.w, eb1.w, d2b);
        }
        float s1 = fmaf(-2.f, d1a + d1b, g_esq[p.y]);
        float s2 = fmaf(-2.f, d2a + d2b, g_esq[p.z]);
        int win;
        if (s1 < s2) win = p.y;
        else if (s2 < s1) win = p.z;
        else win = min(p.y, p.z);
        g_bidx[p.x] = win;
    }
}

// ---------------- full fixup: coalesced transposed rescan (rare) ----------------
__global__ void __launch_bounds__(256) full_fixup_kernel(const float* __restrict__ z) {
    __shared__ __align__(16) float4 s_z4[FB][16];
    __shared__ float s_wv[8][FB];
    __shared__ int s_wi[8][FB];
    const int tid = threadIdx.x, lane = tid & 31, wid = tid >> 5;
    const int nflag = g_nfull;
    const int nbatch = (nflag + FB - 1) / FB;

    for (int b = blockIdx.x; b < nbatch; b += gridDim.x) {
        const int base = b * FB;
        const int nb = min(FB, nflag - base);
        if (tid < FB * 16) {
            int k = tid >> 4, j = tid & 15;
            int src = base + (k < nb ? k : 0);
            s_z4[k][j] =
                reinterpret_cast<const float4*>(z + (size_t)g_full[src] * DIM)[j];
        }
        __syncthreads();

        float lb[FB];
        int li[FB];
#pragma unroll
        for (int k = 0; k < FB; k++) { lb[k] = 3.4e38f; li[k] = 0; }

        for (int chunk = 0; chunk < NC / 1024; chunk++) {
            const int cbase = chunk * 1024;
            float acc[4][FB];
#pragma unroll
            for (int q = 0; q < 4; q++)
#pragma unroll
                for (int k = 0; k < FB; k++) acc[q][k] = 0.f;

#pragma unroll
            for (int jg = 0; jg < 16; jg++) {
                float4 zj[FB];
#pragma unroll
                for (int k = 0; k < FB; k++) zj[k] = s_z4[k][jg];
#pragma unroll
                for (int q = 0; q < 4; q++) {
                    float4 e = g_eT4[jg * NC + cbase + q * 256 + tid];
#pragma unroll
                    for (int k = 0; k < FB; k++) {
                        acc[q][k] = fmaf(zj[k].x, e.x, acc[q][k]);
                        acc[q][k] = fmaf(zj[k].y, e.y, acc[q][k]);
                        acc[q][k] = fmaf(zj[k].z, e.z, acc[q][k]);
                        acc[q][k] = fmaf(zj[k].w, e.w, acc[q][k]);
                    }
                }
            }
#pragma unroll
            for (int q = 0; q < 4; q++) {
                const int c = cbase + q * 256 + tid;
                const float esq = g_esq[c];
#pragma unroll
                for (int k = 0; k < FB; k++) {
                    float s = fmaf(-2.f, acc[q][k], esq);
                    if (s < lb[k]) { lb[k] = s; li[k] = c; }
                }
            }
        }

#pragma unroll
        for (int o = 16; o > 0; o >>= 1) {
#pragma unroll
            for (int k = 0; k < FB; k++) {
                float os = __shfl_down_sync(0xffffffffu, lb[k], o);
                int oi = __shfl_down_sync(0xffffffffu, li[k], o);
                if (os < lb[k] || (os == lb[k] && oi < li[k])) { lb[k] = os; li[k] = oi; }
            }
        }
        if (lane == 0) {
#pragma unroll
            for (int k = 0; k < FB; k++) { s_wv[wid][k] = lb[k]; s_wi[wid][k] = li[k]; }
        }
        __syncthreads();
        if (tid < nb) {
            float bv = s_wv[0][tid];
            int bix = s_wi[0][tid];
#pragma unroll
            for (int w = 1; w < 8; w++) {
                float ov = s_wv[w][tid];
                int oi = s_wi[w][tid];
                if (ov < bv || (ov == bv && oi < bix)) { bv = ov; bix = oi; }
            }
            g_bidx[g_full[base + tid]] = bix;
        }
        __syncthreads();
    }
}

// ---------------- gather / straight-through / loss partials ----------------
__global__ void __launch_bounds__(128) quant_kernel(const float* __restrict__ z,
                                                    const float* __restrict__ emb,
                                                    float* __restrict__ out) {
    __shared__ float s_red[128];
    const int v = blockIdx.x * 128 + threadIdx.x;
    const int idx = g_bidx[v];

    const float4* zp = reinterpret_cast<const float4*>(z + (size_t)v * DIM);
    const float4* qp = reinterpret_cast<const float4*>(emb + (size_t)idx * DIM);
    float4* qo = reinterpret_cast<float4*>(out + (size_t)v * DIM);
    float lsum = 0.f;
#pragma unroll
    for (int i = 0; i < 16; i++) {
        float4 zv = zp[i], q = qp[i];
        float dx = q.x - zv.x, dy = q.y - zv.y, dz = q.z - zv.z, dw = q.w - zv.w;
        qo[i] = make_float4(zv.x + dx, zv.y + dy, zv.z + dz, zv.w + dw);
        lsum += dx * dx + dy * dy + dz * dz + dw * dw;
    }
    out[OFF_IDX + v] = (float)idx;

    s_red[threadIdx.x] = lsum;
    __syncthreads();
#pragma unroll
    for (int o = 64; o > 0; o >>= 1) {
        if (threadIdx.x < o) s_red[threadIdx.x] += s_red[threadIdx.x + o];
        __syncthreads();
    }
    if (threadIdx.x == 0) g_partial[blockIdx.x] = s_red[0];
}

// ---------------- final loss reduction ----------------
__global__ void final_kernel(float* __restrict__ out) {
    __shared__ float s[M_BLOCKS];
    int tid = threadIdx.x;
    s[tid] = g_partial[tid];
    __syncthreads();
#pragma unroll
    for (int o = M_BLOCKS / 2; o > 0; o >>= 1) {
        if (tid < o) s[tid] += s[tid + o];
        __syncthreads();
    }
    if (tid == 0) {
        float loss = s[0] / (float)Q_ELEMS;
        out[OFF_VQ] = loss;
        out[OFF_COMMIT] = loss;
    }
}

// ---------------- launch ----------------
extern "C" void kernel_launch(void* const* d_in, const int* in_sizes, int n_in,
                              void* d_out, int out_size) {
    const float* z = (const float*)d_in[0];
    const float* emb = (const float*)d_in[1];
    if (n_in >= 2 && in_sizes[0] < in_sizes[1]) {
        const float* t = z; z = emb; emb = t;
    }
    float* out = (float*)d_out;

    cudaFuncSetAttribute(vq_mma_kernel,
                         cudaFuncAttributeMaxDynamicSharedMemorySize, DYN_SMEM);

    prep_emb_kernel<<<(NC + 255) / 256, 256>>>(emb);
    prep_z_kernel<<<(NV + 255) / 256, 256>>>(z);
    vq_mma_kernel<<<M_BLOCKS, 256, DYN_SMEM>>>();
    pair_fixup_kernel<<<128, 256>>>(z, emb);
    full_fixup_kernel<<<512, 256>>>(z);
    quant_kernel<<<NV / 128, 128>>>(z, emb, out);
    final_kernel<<<1, M_BLOCKS>>>(out);
}

// round 9
// speedup vs baseline: 3.3088x; 1.0072x over previous
#include <cuda_runtime.h>
#include <cuda_fp16.h>
#include <cstdint>

// ---------------- problem constants ----------------
#define NV 32768
#define NC 8192
#define DIM 64
#define Q_ELEMS (NV * DIM)
#define OFF_VQ Q_ELEMS
#define OFF_COMMIT (Q_ELEMS + 1)
#define OFF_IDX (Q_ELEMS + 2)

#define KP_BYTES 144
#define TILE_M 128
#define TILE_N 64
#define NT (NC / TILE_N)        // 128
#define M_BLOCKS (NV / TILE_M)  // 256
#define TAU 0.35f               // rigorous fp16 score-error cover

// smem: A 128*144=18432 | 3 B stages (64*144=9216 B-tile + 256 esq = 9472)
#define SM_A 0
#define SM_B 18432
#define SM_BSTRIDE 9472
#define SM_ESQ_OFF 9216
#define DYN_SMEM (18432 + 3 * 9472)

#define FB 8
#define QBLOCKS (NV / 64)  // 512 quant blocks

// ---------------- device scratch ----------------
__device__ __align__(16) __half g_eh[NC * DIM];
__device__ __align__(16) float4 g_eT4[16 * NC];
__device__ __align__(16) float g_esq[NC];
__device__ int g_bidx[NV];
__device__ int3 g_pair[NV];
__device__ int g_full[NV];
__device__ int g_npair;
__device__ int g_nfull;
__device__ float g_partial[QBLOCKS];

// ---------------- PTX helpers ----------------
__device__ __forceinline__ uint32_t smem_u32(const void* p) {
    uint32_t a;
    asm("{ .reg .u64 t; cvta.to.shared.u64 t, %1; cvt.u32.u64 %0, t; }" : "=r"(a) : "l"(p));
    return a;
}
__device__ __forceinline__ void cpa16(uint32_t dst, const void* src) {
    asm volatile("cp.async.cg.shared.global [%0], [%1], 16;" :: "r"(dst), "l"(src));
}
#define CP_COMMIT() asm volatile("cp.async.commit_group;" ::: "memory")
#define CP_WAIT(n) asm volatile("cp.async.wait_group %0;" :: "n"(n) : "memory")

__device__ __forceinline__ void ldsm4(uint32_t& r0, uint32_t& r1, uint32_t& r2,
                                      uint32_t& r3, uint32_t addr) {
    asm volatile("ldmatrix.sync.aligned.m8n8.x4.shared.b16 {%0,%1,%2,%3}, [%4];"
                 : "=r"(r0), "=r"(r1), "=r"(r2), "=r"(r3) : "r"(addr));
}
__device__ __forceinline__ void mma16816(float* c, const uint32_t* a, uint32_t b0,
                                         uint32_t b1) {
    asm volatile(
        "mma.sync.aligned.m16n8k16.row.col.f32.f16.f16.f32 "
        "{%0,%1,%2,%3}, {%4,%5,%6,%7}, {%8,%9}, {%0,%1,%2,%3};"
        : "+f"(c[0]), "+f"(c[1]), "+f"(c[2]), "+f"(c[3])
        : "r"(a[0]), "r"(a[1]), "r"(a[2]), "r"(a[3]), "r"(b0), "r"(b1));
}

__device__ __forceinline__ void merge3(float& b1, float& b2, float& b3, int& i1, int& i2,
                                       float c1, float c2, float c3, int j1, int j2) {
    if (c1 < b1 || (c1 == b1 && j1 < i1)) {
        float t; int ti;
        t = b1; b1 = c1; c1 = t; ti = i1; i1 = j1; j1 = ti;
        t = b2; b2 = c2; c2 = t; ti = i2; i2 = j2; j2 = ti;
        t = b3; b3 = c3; c3 = t;
    }
    if (c1 < b2 || (c1 == b2 && j1 < i2)) {
        b3 = fminf(b2, c2);
        b2 = c1; i2 = j1;
    } else {
        b3 = fminf(b3, c1);
    }
}

// ---------------- prep: codebook ----------------
__global__ void prep_emb_kernel(const float* __restrict__ emb) {
    int c = blockIdx.x * blockDim.x + threadIdx.x;
    if (c == 0) { g_npair = 0; g_nfull = 0; }
    if (c >= NC) return;
    const float4* row = reinterpret_cast<const float4*>(emb + (size_t)c * DIM);
    __half2* dst = reinterpret_cast<__half2*>(g_eh + (size_t)c * DIM);
    float s = 0.f;
#pragma unroll
    for (int i = 0; i < 16; i++) {
        float4 v = row[i];
        s += v.x * v.x + v.y * v.y + v.z * v.z + v.w * v.w;
        dst[2 * i] = __halves2half2(__float2half_rn(v.x), __float2half_rn(v.y));
        dst[2 * i + 1] = __halves2half2(__float2half_rn(v.z), __float2half_rn(v.w));
        g_eT4[i * NC + c] = v;
    }
    g_esq[c] = s;
}

// ---------------- main: HMMA distance GEMM + top-3 argmin ----------------
__global__ void __launch_bounds__(256, 2) vq_mma_kernel(const float* __restrict__ z) {
    extern __shared__ __align__(16) char dsm[];
    __shared__ float s_b[2][TILE_M], s_b2[2][TILE_M], s_b3[2][TILE_M];
    __shared__ int s_i[2][TILE_M], s_i2[2][TILE_M];

    const int tid = threadIdx.x;
    const int lane = tid & 31, wid = tid >> 5;
    const int wm = wid & 3, wn = wid >> 2;
    const uint32_t sb = smem_u32(dsm);

    // A tile: fp32 z -> fp16 smem, in-kernel conversion.
    // 1024 destination chunks of 16B (8 halfs); each consumes 2 source float4.
    {
        const float4* asrc =
            reinterpret_cast<const float4*>(z + (size_t)blockIdx.x * TILE_M * DIM);
#pragma unroll
        for (int k = 0; k < 4; k++) {
            int ch = tid + k * 256;          // 0..1023
            int r = ch >> 3, pc = ch & 7;
            float4 f0 = asrc[2 * ch], f1 = asrc[2 * ch + 1];
            __half2 h[4];
            h[0] = __floats2half2_rn(f0.x, f0.y);
            h[1] = __floats2half2_rn(f0.z, f0.w);
            h[2] = __floats2half2_rn(f1.x, f1.y);
            h[3] = __floats2half2_rn(f1.z, f1.w);
            *reinterpret_cast<uint4*>(dsm + SM_A + r * KP_BYTES + pc * 16) =
                *reinterpret_cast<uint4*>(h);
        }
    }

    auto loadB = [&](int t, int stg) {
        uint32_t Bs = sb + SM_B + stg * SM_BSTRIDE;
        const uint4* bsrc =
            reinterpret_cast<const uint4*>(g_eh + (size_t)t * TILE_N * DIM);
#pragma unroll
        for (int i = 0; i < 2; i++) {
            int ch = tid + i * 256;
            int r = ch >> 3, c = ch & 7;
            cpa16(Bs + r * KP_BYTES + c * 16, bsrc + ch);
        }
        if (tid < 16)
            cpa16(Bs + SM_ESQ_OFF + tid * 16,
                  reinterpret_cast<const uint4*>(g_esq + t * TILE_N) + tid);
    };
    loadB(0, 0);
    CP_COMMIT();
    loadB(1, 1);
    CP_COMMIT();

    float b1[4], b2[4], b3[4];
    int i1[4], i2[4];
#pragma unroll
    for (int s = 0; s < 4; s++) {
        b1[s] = 3.4e38f; b2[s] = 3.4e38f; b3[s] = 3.4e38f; i1[s] = 0; i2[s] = 0;
    }

    const uint32_t a_row = wm * 32 + (lane & 15);
    const uint32_t a_koff = (lane >> 4) * 8;
    const uint32_t b_row0 = wn * 32 + ((lane >> 4) * 8) + (lane & 7);
    const uint32_t b_koff = ((lane >> 3) & 1) * 8;
    const int nq = (lane & 3) * 2;

    int st = 0, st2 = 2;
    for (int t = 0; t < NT; t++) {
        if (t + 1 < NT) { CP_WAIT(1); }
        else            { CP_WAIT(0); }
        __syncthreads();  // stage st complete; prior readers of st2 done; A stores visible
        if (t + 2 < NT) { loadB(t + 2, st2); CP_COMMIT(); }

        float acc[2][4][4];
#pragma unroll
        for (int mf = 0; mf < 2; mf++)
#pragma unroll
            for (int nf = 0; nf < 4; nf++)
#pragma unroll
                for (int e = 0; e < 4; e++) acc[mf][nf][e] = 0.f;

        const uint32_t Bs = sb + SM_B + st * SM_BSTRIDE;
#pragma unroll
        for (int ks = 0; ks < DIM / 16; ks++) {
            uint32_t a[2][4];
#pragma unroll
            for (int mf = 0; mf < 2; mf++)
                ldsm4(a[mf][0], a[mf][1], a[mf][2], a[mf][3],
                      sb + SM_A + (a_row + mf * 16) * KP_BYTES +
                          (ks * 16 + a_koff) * 2);
            uint32_t b[4][2];
#pragma unroll
            for (int nh = 0; nh < 2; nh++)
                ldsm4(b[2 * nh][0], b[2 * nh][1], b[2 * nh + 1][0], b[2 * nh + 1][1],
                      Bs + (b_row0 + nh * 16) * KP_BYTES + (ks * 16 + b_koff) * 2);
#pragma unroll
            for (int mf = 0; mf < 2; mf++)
#pragma unroll
                for (int nf = 0; nf < 4; nf++)
                    mma16816(acc[mf][nf], a[mf], b[nf][0], b[nf][1]);
        }

        const float* esq =
            reinterpret_cast<const float*>(dsm + SM_B + st * SM_BSTRIDE + SM_ESQ_OFF);
        float sc[4][8];
#pragma unroll
        for (int mf = 0; mf < 2; mf++) {
#pragma unroll
            for (int nf = 0; nf < 4; nf++) {
                const int n0 = wn * 32 + nf * 8 + nq;
                const float e0 = esq[n0], e1 = esq[n0 + 1];
#pragma unroll
                for (int h = 0; h < 2; h++) {
                    sc[mf * 2 + h][nf * 2 + 0] = fmaf(-2.f, acc[mf][nf][2 * h], e0);
                    sc[mf * 2 + h][nf * 2 + 1] = fmaf(-2.f, acc[mf][nf][2 * h + 1], e1);
                }
            }
        }
#pragma unroll
        for (int s = 0; s < 4; s++) {
            float m01 = fminf(sc[s][0], sc[s][1]);
            float m23 = fminf(sc[s][2], sc[s][3]);
            float m45 = fminf(sc[s][4], sc[s][5]);
            float m67 = fminf(sc[s][6], sc[s][7]);
            float tmin = fminf(fminf(m01, m23), fminf(m45, m67));
            if (tmin < b3[s]) {
#pragma unroll
                for (int k = 0; k < 8; k++) {
                    float v = sc[s][k];
                    int idx = t * TILE_N + wn * 32 + (k >> 1) * 8 + nq + (k & 1);
                    if (v < b1[s]) {
                        b3[s] = b2[s]; b2[s] = b1[s]; i2[s] = i1[s];
                        b1[s] = v; i1[s] = idx;
                    } else if (v < b2[s]) {
                        b3[s] = b2[s]; b2[s] = v; i2[s] = idx;
                    } else if (v < b3[s]) {
                        b3[s] = v;
                    }
                }
            }
        }
        st = (st == 2) ? 0 : st + 1;
        st2 = (st2 == 2) ? 0 : st2 + 1;
    }

#pragma unroll
    for (int o = 1; o < 4; o <<= 1) {
#pragma unroll
        for (int s = 0; s < 4; s++) {
            float c1 = __shfl_xor_sync(0xffffffffu, b1[s], o);
            float c2 = __shfl_xor_sync(0xffffffffu, b2[s], o);
            float c3 = __shfl_xor_sync(0xffffffffu, b3[s], o);
            int j1 = __shfl_xor_sync(0xffffffffu, i1[s], o);
            int j2 = __shfl_xor_sync(0xffffffffu, i2[s], o);
            merge3(b1[s], b2[s], b3[s], i1[s], i2[s], c1, c2, c3, j1, j2);
        }
    }
    if ((lane & 3) == 0) {
#pragma unroll
        for (int s = 0; s < 4; s++) {
            int row = wm * 32 + (s >> 1) * 16 + (lane >> 2) + (s & 1) * 8;
            s_b[wn][row] = b1[s];
            s_b2[wn][row] = b2[s];
            s_b3[wn][row] = b3[s];
            s_i[wn][row] = i1[s];
            s_i2[wn][row] = i2[s];
        }
    }
    __syncthreads();
    if (tid < TILE_M) {
        float B1 = s_b[0][tid], B2 = s_b2[0][tid], B3 = s_b3[0][tid];
        int I1 = s_i[0][tid], I2 = s_i2[0][tid];
        merge3(B1, B2, B3, I1, I2,
               s_b[1][tid], s_b2[1][tid], s_b3[1][tid], s_i[1][tid], s_i2[1][tid]);
        const int v = blockIdx.x * TILE_M + tid;
        if (B2 - B1 >= TAU) {
            g_bidx[v] = I1;
        } else if (B3 - B1 >= TAU) {
            int p = atomicAdd(&g_npair, 1);
            g_pair[p] = make_int3(v, I1, I2);
        } else {
            int p = atomicAdd(&g_nfull, 1);
            g_full[p] = v;
        }
    }
}

// ---------------- pair fixup ----------------
__global__ void __launch_bounds__(256) pair_fixup_kernel(const float* __restrict__ z,
                                                         const float* __restrict__ emb) {
    const int n = g_npair;
    for (int i = blockIdx.x * blockDim.x + threadIdx.x; i < n;
         i += gridDim.x * blockDim.x) {
        int3 p = g_pair[i];
        const float4* zp = reinterpret_cast<const float4*>(z + (size_t)p.x * DIM);
        const float4* e1 = reinterpret_cast<const float4*>(emb + (size_t)p.y * DIM);
        const float4* e2 = reinterpret_cast<const float4*>(emb + (size_t)p.z * DIM);
        float d1a = 0.f, d1b = 0.f, d2a = 0.f, d2b = 0.f;
#pragma unroll
        for (int j = 0; j < 16; j += 2) {
            float4 zv0 = zp[j], zv1 = zp[j + 1];
            float4 ea0 = e1[j], ea1 = e1[j + 1];
            float4 eb0 = e2[j], eb1 = e2[j + 1];
            d1a = fmaf(zv0.x, ea0.x, d1a); d1a = fmaf(zv0.y, ea0.y, d1a);
            d1a = fmaf(zv0.z, ea0.z, d1a); d1a = fmaf(zv0.w, ea0.w, d1a);
            d1b = fmaf(zv1.x, ea1.x, d1b); d1b = fmaf(zv1.y, ea1.y, d1b);
            d1b = fmaf(zv1.z, ea1.z, d1b); d1b = fmaf(zv1.w, ea1.w, d1b);
            d2a = fmaf(zv0.x, eb0.x, d2a); d2a = fmaf(zv0.y, eb0.y, d2a);
            d2a = fmaf(zv0.z, eb0.z, d2a); d2a = fmaf(zv0.w, eb0.w, d2a);
            d2b = fmaf(zv1.x, eb1.x, d2b); d2b = fmaf(zv1.y, eb1.y, d2b);
            d2b = fmaf(zv1.z, eb1.z, d2b); d2b = fmaf(zv1.w, eb1.w, d2b);
        }
        float s1 = fmaf(-2.f, d1a + d1b, g_esq[p.y]);
        float s2 = fmaf(-2.f, d2a + d2b, g_esq[p.z]);
        int win;
        if (s1 < s2) win = p.y;
        else if (s2 < s1) win = p.z;
        else win = min(p.y, p.z);
        g_bidx[p.x] = win;
    }
}

// ---------------- full fixup (rare) ----------------
__global__ void __launch_bounds__(256) full_fixup_kernel(const float* __restrict__ z) {
    __shared__ __align__(16) float4 s_z4[FB][16];
    __shared__ float s_wv[8][FB];
    __shared__ int s_wi[8][FB];
    const int tid = threadIdx.x, lane = tid & 31, wid = tid >> 5;
    const int nflag = g_nfull;
    const int nbatch = (nflag + FB - 1) / FB;

    for (int b = blockIdx.x; b < nbatch; b += gridDim.x) {
        const int base = b * FB;
        const int nb = min(FB, nflag - base);
        if (tid < FB * 16) {
            int k = tid >> 4, j = tid & 15;
            int src = base + (k < nb ? k : 0);
            s_z4[k][j] =
                reinterpret_cast<const float4*>(z + (size_t)g_full[src] * DIM)[j];
        }
        __syncthreads();

        float lb[FB];
        int li[FB];
#pragma unroll
        for (int k = 0; k < FB; k++) { lb[k] = 3.4e38f; li[k] = 0; }

        for (int chunk = 0; chunk < NC / 1024; chunk++) {
            const int cbase = chunk * 1024;
            float acc[4][FB];
#pragma unroll
            for (int q = 0; q < 4; q++)
#pragma unroll
                for (int k = 0; k < FB; k++) acc[q][k] = 0.f;

#pragma unroll
            for (int jg = 0; jg < 16; jg++) {
                float4 zj[FB];
#pragma unroll
                for (int k = 0; k < FB; k++) zj[k] = s_z4[k][jg];
#pragma unroll
                for (int q = 0; q < 4; q++) {
                    float4 e = g_eT4[jg * NC + cbase + q * 256 + tid];
#pragma unroll
                    for (int k = 0; k < FB; k++) {
                        acc[q][k] = fmaf(zj[k].x, e.x, acc[q][k]);
                        acc[q][k] = fmaf(zj[k].y, e.y, acc[q][k]);
                        acc[q][k] = fmaf(zj[k].z, e.z, acc[q][k]);
                        acc[q][k] = fmaf(zj[k].w, e.w, acc[q][k]);
                    }
                }
            }
#pragma unroll
            for (int q = 0; q < 4; q++) {
                const int c = cbase + q * 256 + tid;
                const float esq = g_esq[c];
#pragma unroll
                for (int k = 0; k < FB; k++) {
                    float s = fmaf(-2.f, acc[q][k], esq);
                    if (s < lb[k]) { lb[k] = s; li[k] = c; }
                }
            }
        }

#pragma unroll
        for (int o = 16; o > 0; o >>= 1) {
#pragma unroll
            for (int k = 0; k < FB; k++) {
                float os = __shfl_down_sync(0xffffffffu, lb[k], o);
                int oi = __shfl_down_sync(0xffffffffu, li[k], o);
                if (os < lb[k] || (os == lb[k] && oi < li[k])) { lb[k] = os; li[k] = oi; }
            }
        }
        if (lane == 0) {
#pragma unroll
            for (int k = 0; k < FB; k++) { s_wv[wid][k] = lb[k]; s_wi[wid][k] = li[k]; }
        }
        __syncthreads();
        if (tid < nb) {
            float bv = s_wv[0][tid];
            int bix = s_wi[0][tid];
#pragma unroll
            for (int w = 1; w < 8; w++) {
                float ov = s_wv[w][tid];
                int oi = s_wi[w][tid];
                if (ov < bv || (ov == bv && oi < bix)) { bv = ov; bix = oi; }
            }
            g_bidx[g_full[base + tid]] = bix;
        }
        __syncthreads();
    }
}

// ---------------- gather / straight-through / loss: 4 threads per voxel ----------------
__global__ void __launch_bounds__(256) quant_kernel(const float* __restrict__ z,
                                                    const float* __restrict__ emb,
                                                    float* __restrict__ out) {
    __shared__ float s_red[64];
    const int tid = threadIdx.x;
    const int vl = tid >> 2, seg = tid & 3;
    const int v = blockIdx.x * 64 + vl;
    const int idx = g_bidx[v];

    const float4* zp = reinterpret_cast<const float4*>(z + (size_t)v * DIM) + seg * 4;
    const float4* qp = reinterpret_cast<const float4*>(emb + (size_t)idx * DIM) + seg * 4;
    float4* qo = reinterpret_cast<float4*>(out + (size_t)v * DIM) + seg * 4;
    float lsum = 0.f;
#pragma unroll
    for (int i = 0; i < 4; i++) {
        float4 zv = zp[i], q = qp[i];
        float dx = q.x - zv.x, dy = q.y - zv.y, dz = q.z - zv.z, dw = q.w - zv.w;
        qo[i] = make_float4(zv.x + dx, zv.y + dy, zv.z + dz, zv.w + dw);
        lsum += dx * dx + dy * dy + dz * dz + dw * dw;
    }
    if (seg == 0) out[OFF_IDX + v] = (float)idx;

    lsum += __shfl_down_sync(0xffffffffu, lsum, 2);
    lsum += __shfl_down_sync(0xffffffffu, lsum, 1);
    if (seg == 0) s_red[vl] = lsum;
    __syncthreads();
#pragma unroll
    for (int o = 32; o > 0; o >>= 1) {
        if (tid < o) s_red[tid] += s_red[tid + o];
        __syncthreads();
    }
    if (tid == 0) g_partial[blockIdx.x] = s_red[0];
}

// ---------------- final loss reduction ----------------
__global__ void final_kernel(float* __restrict__ out) {
    __shared__ float s[256];
    int tid = threadIdx.x;
    s[tid] = g_partial[tid] + g_partial[tid + 256];
    __syncthreads();
#pragma unroll
    for (int o = 128; o > 0; o >>= 1) {
        if (tid < o) s[tid] += s[tid + o];
        __syncthreads();
    }
    if (tid == 0) {
        float loss = s[0] / (float)Q_ELEMS;
        out[OFF_VQ] = loss;
        out[OFF_COMMIT] = loss;
    }
}

// ---------------- launch ----------------
extern "C" void kernel_launch(void* const* d_in, const int* in_sizes, int n_in,
                              void* d_out, int out_size) {
    const float* z = (const float*)d_in[0];
    const float* emb = (const float*)d_in[1];
    if (n_in >= 2 && in_sizes[0] < in_sizes[1]) {
        const float* t = z; z = emb; emb = t;
    }
    float* out = (float*)d_out;

    cudaFuncSetAttribute(vq_mma_kernel,
                         cudaFuncAttributeMaxDynamicSharedMemorySize, DYN_SMEM);

    prep_emb_kernel<<<(NC + 255) / 256, 256>>>(emb);
    vq_mma_kernel<<<M_BLOCKS, 256, DYN_SMEM>>>(z);
    pair_fixup_kernel<<<128, 256>>>(z, emb);
    full_fixup_kernel<<<512, 256>>>(z);
    quant_kernel<<<QBLOCKS, 256>>>(z, emb, out);
    final_kernel<<<1, 256>>>(out);
}